// round 16
// baseline (speedup 1.0000x reference)
#include <cuda_runtime.h>
#include <math.h>

#define N      4096
#define DIMS   8
#define REGL   1e-3f
#define ITER   33                // gbars = 2 + ITER + 1 = 36 (even -> replay-safe)
#define GRID   296               // 2 blocks per SM exactly (148 SMs)
#define BLOCK  512
#define NWARP  (BLOCK / 32)      // 16
#define VPT    (N / 4 / BLOCK)   // 2
#define MAXR   14                // blocks 0..247 own 14 rows, 248..295 own 13
#define SP     17
#define NT64   64
#define BJOBS  (NT64 * (NT64 + 1) / 2)   // 2080 tile jobs (build AND matvec)
#define QSCALE    4398046511104.0f       // 2^42
#define QINVSCALE 2.2737367544323206e-13f

// ---------------- device scratch ----------------
__device__ float4 d_ftr[DIMS * N];
__device__ float  d_ntr[N];
__device__ float4 d_fte[DIMS * N];
__device__ float  d_nte[N];
__device__ float  d_A [(size_t)N * N];            // upper 64-tiles + diag only
__device__ float  d_x[N];
__device__ long long d_qfix[3][N];                // triple-buffered fixed-point q

// ---------------- flag-tree grid barrier (sense-reversing) ----------------
__device__ volatile unsigned d_flag[GRID];
__device__ volatile unsigned d_rel;

__device__ __forceinline__ void gbar(unsigned* lsense) {
    const unsigned s = *lsense ^ 1u;
    *lsense = s;
    __syncthreads();
    if (blockIdx.x == 0) {
        __threadfence();
        const int t = threadIdx.x;
        if (t >= 1 && t < GRID) { while (d_flag[t] != s) { } }
        __syncthreads();
        if (t == 0) { __threadfence(); d_rel = s; }
        __threadfence();
    } else {
        if (threadIdx.x == 0) {
            __threadfence();
            d_flag[blockIdx.x] = s;
            while (d_rel != s) { }
            __threadfence();
        }
    }
    __syncthreads();
}

// four dots reduced in ONE round; results in s_bc[0..3] (identical in every block)
__device__ __forceinline__ void block_sum4(float a, float b, float c, float d,
                                           float* s_red4, float* s_bc) {
    const int warp = threadIdx.x >> 5, lane = threadIdx.x & 31;
#pragma unroll
    for (int o = 16; o; o >>= 1) {
        a += __shfl_xor_sync(0xffffffffu, a, o);
        b += __shfl_xor_sync(0xffffffffu, b, o);
        c += __shfl_xor_sync(0xffffffffu, c, o);
        d += __shfl_xor_sync(0xffffffffu, d, o);
    }
    if (lane == 0) {
        s_red4[warp * 4 + 0] = a;
        s_red4[warp * 4 + 1] = b;
        s_red4[warp * 4 + 2] = c;
        s_red4[warp * 4 + 3] = d;
    }
    __syncthreads();
    if (warp == 0) {
        float ta = (lane < NWARP) ? s_red4[lane * 4 + 0] : 0.f;
        float tb = (lane < NWARP) ? s_red4[lane * 4 + 1] : 0.f;
        float tc = (lane < NWARP) ? s_red4[lane * 4 + 2] : 0.f;
        float td = (lane < NWARP) ? s_red4[lane * 4 + 3] : 0.f;
#pragma unroll
        for (int o = 8; o; o >>= 1) {
            ta += __shfl_xor_sync(0xffffffffu, ta, o);
            tb += __shfl_xor_sync(0xffffffffu, tb, o);
            tc += __shfl_xor_sync(0xffffffffu, tc, o);
            td += __shfl_xor_sync(0xffffffffu, td, o);
        }
        if (lane == 0) { s_bc[0] = ta; s_bc[1] = tb; s_bc[2] = tc; s_bc[3] = td; }
    }
    __syncthreads();
}

// triangular decode over 64 tiles: t in [0, 2080) -> (I <= J)
__device__ __forceinline__ void tri64(int t, int* Io, int* Jo) {
    int I = 0;
    while (t >= NT64 - I) { t -= NT64 - I; I++; }
    *Io = I; *Jo = I + t;
}

__device__ __forceinline__ void qfix_add(long long* addr, float v) {
    atomicAdd((unsigned long long*)addr,
              (unsigned long long)(long long)__float2ll_rn(v * QSCALE));
}

// ---------------- the whole pipeline in one persistent kernel ----------------
__global__ __launch_bounds__(BLOCK, 2)
void mega_kernel(const float* __restrict__ Xtr, const float* __restrict__ ytr,
                 const float* __restrict__ Xte, float* __restrict__ out) {
    __shared__ __align__(16) float s_p[N];      // full p (identical in all blocks)
    __shared__ __align__(16) float s_r[N];      // full r
    __shared__ __align__(16) char  s_scr[8192]; // build/predict tiles; matvec v-reduce [16][64]
    __shared__ float  s_tn[64];
    __shared__ float  s_red[NWARP * 4];
    __shared__ float  s_part[NWARP * SP];
    __shared__ float  s_bc[4];

    unsigned lsense = 0;
    const int tid = threadIdx.x, blk = blockIdx.x;
    const int warp = tid >> 5, lane = tid & 31;

    const int start = blk * 13 + (blk < 248 ? blk : 248);
    const int cnt   = (blk < 248) ? 14 : 13;

    // ===== Phase A: features + zero qfix buffers + x init =====
    for (int i = blk * BLOCK + tid; i < 2 * N; i += GRID * BLOCK) {
        const int   j  = (i < N) ? i : i - N;
        const float* X = (i < N) ? Xtr : Xte;
        float4* fd = (i < N) ? d_ftr : d_fte;
        float*  fn = (i < N) ? d_ntr : d_nte;
        float nrm = 0.f;
#pragma unroll
        for (int d = 0; d < DIMS; d++) {
            float v = X[j * DIMS + d];
            nrm = fmaf(v, v, nrm);
            float s, c;
            __sincosf(0.5f * v, &s, &c);
            fd[d * N + j] = make_float4(v, c, s, 0.f);
        }
        fn[j] = nrm;
    }
    for (int i = blk * BLOCK + tid; i < 3 * N; i += GRID * BLOCK)
        __stcg(&((long long*)d_qfix)[i], 0ll);
    if (tid < cnt) d_x[start + tid] = 0.f;
    gbar(&lsense);                                                   // bar 1

    // ===== Phase B: build ONLY upper-triangle 64x64 tiles (no mirror) =====
    {
        float4* tf = (float4*)s_scr;   // [8][64]
        for (int t = blk; t < BJOBS; t += GRID) {
            int I, J;
            tri64(t, &I, &J);
            const int gr = I * 64, gc = J * 64;

            for (int k = tid; k < 8 * 64; k += BLOCK) {
                int d = k >> 6, idx = k & 63;
                tf[d * 64 + idx] = d_ftr[d * N + gr + idx];
            }
            if (tid < 64) s_tn[tid] = d_ntr[gr + tid];
            __syncthreads();

            const int cL = tid & 63, chunk = tid >> 6;
            const int c = gc + cL;
            float4 cf[DIMS];
#pragma unroll
            for (int d = 0; d < DIMS; d++) cf[d] = d_ftr[d * N + c];
            const float cn = d_ntr[c];

#pragma unroll
            for (int rr = 0; rr < 8; rr++) {
                const int rowL = chunk * 8 + rr;
                float dot = 0.f, prod = 1.f;
#pragma unroll
                for (int d = 0; d < DIMS; d++) {
                    float4 rf = tf[d * 64 + rowL];
                    dot  = fmaf(rf.x, cf[d].x, dot);
                    prod *= fmaf(rf.z, cf[d].z, rf.y * cf[d].y);
                }
                float sq = s_tn[rowL] + cn - 2.f * dot;
                float v  = __expf(-sq) * fabsf(prod);
                const int r = gr + rowL;
                if (r == c) v += REGL;
                d_A[(size_t)r * N + c] = v;
            }
            __syncthreads();
        }
    }

    // ===== CG init: r = p = y (rs computed exactly in-loop) =====
    for (int i = tid; i < N; i += BLOCK) {
        float v = ytr[i];
        s_r[i] = v; s_p[i] = v;
    }
    gbar(&lsense);                                                   // bar 2 (covers build)

    // ===== CG loop: symmetric matvec via int64 atomics; 1 barrier/iter =====
    for (int it = 0; it < ITER; it++) {
        long long* qf = d_qfix[it % 3];

        // --- matvec tiles: warp = 4 rows of a 64x64 tile; float2 per lane ---
        for (int t = blk; t < BJOBS; t += GRID) {
            int I, J;
            tri64(t, &I, &J);
            const int gr = I * 64, gc = J * 64;
            const bool diag = (I == J);
            const float2 pjl = ((const float2*)(s_p + gc))[lane];
            const int r0 = warp * 4;
            float2 vacc = make_float2(0.f, 0.f);
#pragma unroll
            for (int k = 0; k < 4; k++) {
                const float2* Ar = (const float2*)(d_A + (size_t)(gr + r0 + k) * N + gc);
                float2 a = __ldcg(Ar + lane);
                float uk = fmaf(a.x, pjl.x, a.y * pjl.y);
                if (!diag) {
                    float pi = s_p[gr + r0 + k];
                    vacc.x = fmaf(a.x, pi, vacc.x);
                    vacc.y = fmaf(a.y, pi, vacc.y);
                }
#pragma unroll
                for (int o = 16; o; o >>= 1) uk += __shfl_xor_sync(0xffffffffu, uk, o);
                if (lane == 0) qfix_add(qf + gr + r0 + k, uk);
            }
            if (!diag) {
                float* sv = (float*)s_scr;                 // [16][64]
                sv[warp * 64 + lane * 2]     = vacc.x;
                sv[warp * 64 + lane * 2 + 1] = vacc.y;
                __syncthreads();
                if (tid < 64) {
                    float s = 0.f;
#pragma unroll
                    for (int w = 0; w < NWARP; w++) s += sv[w * 64 + tid];
                    qfix_add(qf + gc + tid, s);
                }
                __syncthreads();
            }
        }
        gbar(&lsense);                                               // bar (it+3): all q visible

        // --- pass 1 (read-only): qfix->float regs; dots pq,rq,qq,rr(EXACT) ---
        const float p_own = (tid < cnt) ? s_p[start + tid] : 0.f;
        float4 qv[VPT];
        float pq = 0.f, rq = 0.f, qq = 0.f, rr2 = 0.f;
#pragma unroll
        for (int k = 0; k < VPT; k++) {
            const int i = tid + k * BLOCK;
            const long long* qp = qf + i * 4;
            float qx = __ll2float_rn(__ldcg(qp + 0)) * QINVSCALE;
            float qy = __ll2float_rn(__ldcg(qp + 1)) * QINVSCALE;
            float qz = __ll2float_rn(__ldcg(qp + 2)) * QINVSCALE;
            float qw = __ll2float_rn(__ldcg(qp + 3)) * QINVSCALE;
            qv[k] = make_float4(qx, qy, qz, qw);
            float4 pv = ((const float4*)s_p)[i];
            float4 rv = ((const float4*)s_r)[i];
            pq = fmaf(qx, pv.x, fmaf(qy, pv.y, fmaf(qz, pv.z, fmaf(qw, pv.w, pq))));
            rq = fmaf(qx, rv.x, fmaf(qy, rv.y, fmaf(qz, rv.z, fmaf(qw, rv.w, rq))));
            qq = fmaf(qx, qx, fmaf(qy, qy, fmaf(qz, qz, fmaf(qw, qw, qq))));
            rr2 = fmaf(rv.x, rv.x, fmaf(rv.y, rv.y,
                  fmaf(rv.z, rv.z, fmaf(rv.w, rv.w, rr2))));
        }
        block_sum4(pq, rq, qq, rr2, s_red, s_bc);
        const float pAp = s_bc[0];
        const float rqS = s_bc[1];
        const float qqS = s_bc[2];
        const float rs  = s_bc[3];                 // exact ||r||^2 -> alpha never drifts
        const float alpha = (pAp > 0.f && rs > 0.f) ? rs / pAp : 0.f;
        float rsnew = fmaf(alpha * alpha, qqS, fmaf(-2.f * alpha, rqS, rs));
        rsnew = fmaxf(rsnew, 0.f);                 // recurrence only for beta (one-shot)
        const float beta = (rs > 0.f) ? rsnew / rs : 0.f;

        // zero the buffer to be used at iter it+2 (two barriers before its atomics)
        if (tid < cnt) __stcg(&d_qfix[(it + 2) % 3][start + tid], 0ll);

        // x own rows (snapshot)
        if (tid < cnt) {
            int e = start + tid;
            d_x[e] = fmaf(alpha, p_own, d_x[e]);
        }

        // --- pass 2 (fused): r -= alpha*q ; p = r + beta*p ---
#pragma unroll
        for (int k = 0; k < VPT; k++) {
            const int i = tid + k * BLOCK;
            float4 rv = ((float4*)s_r)[i];
            rv.x = fmaf(-alpha, qv[k].x, rv.x);
            rv.y = fmaf(-alpha, qv[k].y, rv.y);
            rv.z = fmaf(-alpha, qv[k].z, rv.z);
            rv.w = fmaf(-alpha, qv[k].w, rv.w);
            ((float4*)s_r)[i] = rv;
            float4 pv = ((float4*)s_p)[i];
            pv.x = fmaf(beta, pv.x, rv.x);
            pv.y = fmaf(beta, pv.y, rv.y);
            pv.z = fmaf(beta, pv.z, rv.z);
            pv.w = fmaf(beta, pv.w, rv.w);
            ((float4*)s_p)[i] = pv;
        }
        __syncthreads();
    }
    gbar(&lsense);                                                   // bar: x complete

    // ===== Predict (fused): y_pred[own rows] = K(test_rows, :) @ x =====
#pragma unroll
    for (int k = 0; k < VPT; k++) {
        const int i = tid + k * BLOCK;
        ((float4*)s_p)[i] = __ldcg(((const float4*)d_x) + i);
    }
    {
        float4* tfp = (float4*)s_scr;   // [8][MAXR]
        for (int k = tid; k < MAXR * DIMS; k += BLOCK) {
            int d = k / MAXR, rr = k % MAXR;
            int row = start + ((rr < cnt) ? rr : 0);
            tfp[d * MAXR + rr] = d_fte[d * N + row];
        }
        if (tid < MAXR) s_tn[tid] = d_nte[start + ((tid < cnt) ? tid : 0)];
        __syncthreads();

        float acc[MAXR];
#pragma unroll
        for (int rr = 0; rr < MAXR; rr++) acc[rr] = 0.f;

        for (int ct = 0; ct < 8; ct++) {
            const int col = ct * 512 + tid;
            float4 cf[DIMS];
#pragma unroll
            for (int d = 0; d < DIMS; d++) cf[d] = d_ftr[d * N + col];
            const float cn = d_ntr[col];
            const float xv = s_p[col];

#pragma unroll 2
            for (int rr = 0; rr < MAXR; rr++) {
                float dot = 0.f, prod = 1.f;
#pragma unroll
                for (int d = 0; d < DIMS; d++) {
                    float4 rf = tfp[d * MAXR + rr];
                    dot  = fmaf(rf.x, cf[d].x, dot);
                    prod *= fmaf(rf.z, cf[d].z, rf.y * cf[d].y);
                }
                float sq = s_tn[rr] + cn - 2.f * dot;
                acc[rr] = fmaf(__expf(-sq) * fabsf(prod), xv, acc[rr]);
            }
        }
#pragma unroll
        for (int rr = 0; rr < MAXR; rr++) {
            float v = acc[rr];
#pragma unroll
            for (int o = 16; o; o >>= 1) v += __shfl_xor_sync(0xffffffffu, v, o);
            if (lane == 0) s_part[warp * SP + rr] = v;
        }
        __syncthreads();
        if (tid < cnt) {
            float s = 0.f;
#pragma unroll
            for (int w = 0; w < NWARP; w++) s += s_part[w * SP + tid];
            out[start + tid] = s;
        }
    }
    // total gbar calls: 2 + ITER + 1 = 36 (even) -> replay-safe
}

// ---------------- launch ----------------
extern "C" void kernel_launch(void* const* d_in, const int* in_sizes, int n_in,
                              void* d_out, int out_size) {
    const float* Xtr = (const float*)d_in[0];
    const float* ytr = (const float*)d_in[1];
    const float* Xte = (const float*)d_in[2];
    mega_kernel<<<GRID, BLOCK>>>(Xtr, ytr, Xte, (float*)d_out);
}

// round 17
// speedup vs baseline: 2.1769x; 2.1769x over previous
#include <cuda_runtime.h>
#include <math.h>

#define N      4096
#define DIMS   8
#define REGL   1e-3f
#define ITER   32                // gbars = 2 + ITER + 1 + 1 filler = 36 (even -> replay-safe)
#define GRID   296               // 2 blocks per SM exactly (148 SMs)
#define BLOCK  512
#define NWARP  (BLOCK / 32)      // 16
#define VPT    (N / 4 / BLOCK)   // 2
#define MAXR   14                // blocks 0..247 own 14 rows, 248..295 own 13
#define SP     17
#define NT64   64
#define BJOBS  (NT64 * (NT64 + 1) / 2)   // 2080 build jobs

// ---------------- device scratch ----------------
__device__ float4 d_ftr[DIMS * N];
__device__ float  d_ntr[N];
__device__ float4 d_fte[DIMS * N];
__device__ float  d_nte[N];
__device__ float  d_A [(size_t)N * N];    // 64 MB, symmetric (stored full)
__device__ float  d_x[N];
__device__ float  d_q0[N], d_q1[N];       // double-buffered A*p

// ---------------- split grid barrier (sense-reversing, acquire/release) ----------------
__device__ volatile unsigned d_flag[GRID];
__device__ volatile unsigned d_rel;

__device__ __forceinline__ void rel_store(volatile unsigned* a, unsigned v) {
    asm volatile("st.release.gpu.global.u32 [%0], %1;" :: "l"((void*)a), "r"(v) : "memory");
}
__device__ __forceinline__ unsigned acq_load(volatile unsigned* a) {
    unsigned v;
    asm volatile("ld.acquire.gpu.global.u32 %0, [%1];" : "=r"(v) : "l"((void*)a) : "memory");
    return v;
}

// arrive: flip sense, sync block, non-zero blocks publish their flag
__device__ __forceinline__ void gbar_arrive(unsigned* lsense) {
    const unsigned s = *lsense ^ 1u;
    *lsense = s;
    __syncthreads();
    if (blockIdx.x != 0 && threadIdx.x == 0) rel_store(&d_flag[blockIdx.x], s);
}
// wait: block0 collects flags then releases; others spin on release word
__device__ __forceinline__ void gbar_wait(unsigned* lsense) {
    const unsigned s = *lsense;
    if (blockIdx.x == 0) {
        const int t = threadIdx.x;
        if (t >= 1 && t < GRID) { while (acq_load(&d_flag[t]) != s) { } }
        __syncthreads();
        if (t == 0) rel_store(&d_rel, s);
    } else {
        if (threadIdx.x == 0) { while (acq_load(&d_rel) != s) { } }
    }
    __syncthreads();
}
__device__ __forceinline__ void gbar(unsigned* lsense) {
    gbar_arrive(lsense);
    gbar_wait(lsense);
}

// reduce 3 dots (one round) + fold precomputed per-warp rr partials from s_rr
__device__ __forceinline__ void block_sum3_rr(float a, float b, float c,
                                              const float* s_rr,
                                              float* s_red3, float* s_bc) {
    const int warp = threadIdx.x >> 5, lane = threadIdx.x & 31;
#pragma unroll
    for (int o = 16; o; o >>= 1) {
        a += __shfl_xor_sync(0xffffffffu, a, o);
        b += __shfl_xor_sync(0xffffffffu, b, o);
        c += __shfl_xor_sync(0xffffffffu, c, o);
    }
    if (lane == 0) {
        s_red3[warp * 3 + 0] = a;
        s_red3[warp * 3 + 1] = b;
        s_red3[warp * 3 + 2] = c;
    }
    __syncthreads();
    if (warp == 0) {
        float ta = (lane < NWARP) ? s_red3[lane * 3 + 0] : 0.f;
        float tb = (lane < NWARP) ? s_red3[lane * 3 + 1] : 0.f;
        float tc = (lane < NWARP) ? s_red3[lane * 3 + 2] : 0.f;
        float td = (lane < NWARP) ? s_rr[lane] : 0.f;
#pragma unroll
        for (int o = 8; o; o >>= 1) {
            ta += __shfl_xor_sync(0xffffffffu, ta, o);
            tb += __shfl_xor_sync(0xffffffffu, tb, o);
            tc += __shfl_xor_sync(0xffffffffu, tc, o);
            td += __shfl_xor_sync(0xffffffffu, td, o);
        }
        if (lane == 0) { s_bc[0] = ta; s_bc[1] = tb; s_bc[2] = tc; s_bc[3] = td; }
    }
    __syncthreads();
}

// triangular decode over 64 tiles: t in [0, 2080) -> (I <= J)
__device__ __forceinline__ void tri64(int t, int* Io, int* Jo) {
    int I = 0;
    while (t >= NT64 - I) { t -= NT64 - I; I++; }
    *Io = I; *Jo = I + t;
}

// ---------------- the whole pipeline in one persistent kernel ----------------
__global__ __launch_bounds__(BLOCK, 2)
void mega_kernel(const float* __restrict__ Xtr, const float* __restrict__ ytr,
                 const float* __restrict__ Xte, float* __restrict__ out) {
    __shared__ __align__(16) float s_p[N];      // full p (identical in all blocks)
    __shared__ __align__(16) float s_r[N];      // full r
    __shared__ __align__(16) char  s_scr[8192];
    __shared__ float  s_tn[64];
    __shared__ float  s_red[NWARP * 3];
    __shared__ float  s_rr[NWARP];
    __shared__ float  s_part[NWARP * SP];
    __shared__ float  s_bc[4];

    unsigned lsense = 0;
    const int tid = threadIdx.x, blk = blockIdx.x;
    const int warp = tid >> 5, lane = tid & 31;

    const int start = blk * 13 + (blk < 248 ? blk : 248);
    const int cnt   = (blk < 248) ? 14 : 13;

    // ===== Phase A: features =====
    for (int i = blk * BLOCK + tid; i < 2 * N; i += GRID * BLOCK) {
        const int   j  = (i < N) ? i : i - N;
        const float* X = (i < N) ? Xtr : Xte;
        float4* fd = (i < N) ? d_ftr : d_fte;
        float*  fn = (i < N) ? d_ntr : d_nte;
        float nrm = 0.f;
#pragma unroll
        for (int d = 0; d < DIMS; d++) {
            float v = X[j * DIMS + d];
            nrm = fmaf(v, v, nrm);
            float s, c;
            __sincosf(0.5f * v, &s, &c);
            fd[d * N + j] = make_float4(v, c, s, 0.f);
        }
        fn[j] = nrm;
    }
    if (tid < cnt) d_x[start + tid] = 0.f;
    gbar(&lsense);                                                   // bar 1

    // ===== Phase B: symmetric build, 64x64 upper-triangle tiles + mirror =====
    {
        float4* tf = (float4*)s_scr;   // [8][64]
        for (int t = blk; t < BJOBS; t += GRID) {
            int I, J;
            tri64(t, &I, &J);
            const int gr = I * 64, gc = J * 64;

            for (int k = tid; k < 8 * 64; k += BLOCK) {
                int d = k >> 6, idx = k & 63;
                tf[d * 64 + idx] = d_ftr[d * N + gr + idx];
            }
            if (tid < 64) s_tn[tid] = d_ntr[gr + tid];
            __syncthreads();

            const int cL = tid & 63, chunk = tid >> 6;
            const int c = gc + cL;
            float4 cf[DIMS];
#pragma unroll
            for (int d = 0; d < DIMS; d++) cf[d] = d_ftr[d * N + c];
            const float cn = d_ntr[c];

            float val[8];
#pragma unroll
            for (int rr = 0; rr < 8; rr++) {
                const int rowL = chunk * 8 + rr;
                float dot = 0.f, prod = 1.f;
#pragma unroll
                for (int d = 0; d < DIMS; d++) {
                    float4 rf = tf[d * 64 + rowL];
                    dot  = fmaf(rf.x, cf[d].x, dot);
                    prod *= fmaf(rf.z, cf[d].z, rf.y * cf[d].y);
                }
                float sq = s_tn[rowL] + cn - 2.f * dot;
                float v  = __expf(-sq) * fabsf(prod);
                const int r = gr + rowL;
                if (r == c) v += REGL;
                val[rr] = v;
                d_A[(size_t)r * N + c] = v;
            }
            if (I != J) {
                float* mrow = d_A + (size_t)c * N + gr + chunk * 8;
                ((float4*)mrow)[0] = make_float4(val[0], val[1], val[2], val[3]);
                ((float4*)mrow)[1] = make_float4(val[4], val[5], val[6], val[7]);
            }
            __syncthreads();
        }
    }

    // ===== CG init: r = p = y (rs computed exactly via in-loop rr) =====
    for (int i = tid; i < N; i += BLOCK) {
        float v = ytr[i];
        s_r[i] = v; s_p[i] = v;
    }
    gbar(&lsense);                                                   // bar 2 (covers build)

    // ===== CG loop: 1 split barrier; rr hidden under barrier drain =====
    for (int it = 0; it < ITER; it++) {
        float* qb = (it & 1) ? d_q1 : d_q0;

        // --- q[own rows] = A * p: warp-per-256-col slice, p slice in regs ---
        {
            const float4* pv4 = ((const float4*)s_p) + warp * 64;
            const float4  b0  = pv4[lane];
            const float4  b1  = pv4[lane + 32];
            float accr[MAXR];
#pragma unroll
            for (int r = 0; r < MAXR; r++) {
                const int rr = (r < cnt) ? r : 0;
                const float4* Ar = (const float4*)(d_A + (size_t)(start + rr) * N) + warp * 64;
                float4 a0 = __ldcg(Ar + lane);
                float4 a1 = __ldcg(Ar + lane + 32);
                float d0 = fmaf(a0.x, b0.x, fmaf(a0.y, b0.y, fmaf(a0.z, b0.z, a0.w * b0.w)));
                float d1 = fmaf(a1.x, b1.x, fmaf(a1.y, b1.y, fmaf(a1.z, b1.z, a1.w * b1.w)));
                accr[r] = d0 + d1;
            }
#pragma unroll
            for (int r = 0; r < MAXR; r++) {
                float v = accr[r];
#pragma unroll
                for (int o = 16; o; o >>= 1) v += __shfl_xor_sync(0xffffffffu, v, o);
                if (lane == 0) s_part[warp * SP + r] = v;
            }
        }
        __syncthreads();
        if (tid < cnt) {
            float s = 0.f;
#pragma unroll
            for (int w = 0; w < NWARP; w++) s += s_part[w * SP + tid];
            qb[start + tid] = s;
        }
        gbar_arrive(&lsense);                        // publish q; barrier starts draining

        // --- hidden under barrier: rr = ||r||^2 partials (needs only s_r) ---
        {
            float rr2 = 0.f;
#pragma unroll
            for (int k = 0; k < VPT; k++) {
                const int i = tid + k * BLOCK;
                float4 rv = ((const float4*)s_r)[i];
                rr2 = fmaf(rv.x, rv.x, fmaf(rv.y, rv.y,
                      fmaf(rv.z, rv.z, fmaf(rv.w, rv.w, rr2))));
            }
#pragma unroll
            for (int o = 16; o; o >>= 1) rr2 += __shfl_xor_sync(0xffffffffu, rr2, o);
            if (lane == 0) s_rr[warp] = rr2;
        }
        gbar_wait(&lsense);                          // all q visible

        // --- pass 1 (read-only): q->regs; dots pq, rq, qq; snapshot own p ---
        const float p_own = (tid < cnt) ? s_p[start + tid] : 0.f;
        float4 qv[VPT];
        float pq = 0.f, rq = 0.f, qq = 0.f;
#pragma unroll
        for (int k = 0; k < VPT; k++) {
            const int i = tid + k * BLOCK;
            qv[k] = __ldcg(((const float4*)qb) + i);
            float4 pv = ((const float4*)s_p)[i];
            float4 rv = ((const float4*)s_r)[i];
            pq = fmaf(qv[k].x, pv.x, fmaf(qv[k].y, pv.y,
                 fmaf(qv[k].z, pv.z, fmaf(qv[k].w, pv.w, pq))));
            rq = fmaf(qv[k].x, rv.x, fmaf(qv[k].y, rv.y,
                 fmaf(qv[k].z, rv.z, fmaf(qv[k].w, rv.w, rq))));
            qq = fmaf(qv[k].x, qv[k].x, fmaf(qv[k].y, qv[k].y,
                 fmaf(qv[k].z, qv[k].z, fmaf(qv[k].w, qv[k].w, qq))));
        }
        block_sum3_rr(pq, rq, qq, s_rr, s_red, s_bc);
        const float pAp = s_bc[0];
        const float rqS = s_bc[1];
        const float qqS = s_bc[2];
        const float rs  = s_bc[3];                 // exact ||r||^2 -> alpha never drifts
        const float alpha = (pAp > 0.f && rs > 0.f) ? rs / pAp : 0.f;
        float rsnew = fmaf(alpha * alpha, qqS, fmaf(-2.f * alpha, rqS, rs));
        rsnew = fmaxf(rsnew, 0.f);                 // recurrence only for beta (one-shot)
        const float beta = (rs > 0.f) ? rsnew / rs : 0.f;

        // x own rows (snapshot; no s_p read after writes start)
        if (tid < cnt) {
            int e = start + tid;
            d_x[e] = fmaf(alpha, p_own, d_x[e]);
        }

        // --- pass 2 (fused): r -= alpha*q ; p = r + beta*p ---
#pragma unroll
        for (int k = 0; k < VPT; k++) {
            const int i = tid + k * BLOCK;
            float4 rv = ((float4*)s_r)[i];
            rv.x = fmaf(-alpha, qv[k].x, rv.x);
            rv.y = fmaf(-alpha, qv[k].y, rv.y);
            rv.z = fmaf(-alpha, qv[k].z, rv.z);
            rv.w = fmaf(-alpha, qv[k].w, rv.w);
            ((float4*)s_r)[i] = rv;
            float4 pv = ((float4*)s_p)[i];
            pv.x = fmaf(beta, pv.x, rv.x);
            pv.y = fmaf(beta, pv.y, rv.y);
            pv.z = fmaf(beta, pv.z, rv.z);
            pv.w = fmaf(beta, pv.w, rv.w);
            ((float4*)s_p)[i] = pv;
        }
        __syncthreads();
    }
    gbar(&lsense);                                                   // bar: x complete

    // ===== Predict (fused): y_pred[own rows] = K(test_rows, :) @ x =====
#pragma unroll
    for (int k = 0; k < VPT; k++) {
        const int i = tid + k * BLOCK;
        ((float4*)s_p)[i] = __ldcg(((const float4*)d_x) + i);
    }
    {
        float4* tfp = (float4*)s_scr;   // [8][MAXR]
        for (int k = tid; k < MAXR * DIMS; k += BLOCK) {
            int d = k / MAXR, rr = k % MAXR;
            int row = start + ((rr < cnt) ? rr : 0);
            tfp[d * MAXR + rr] = d_fte[d * N + row];
        }
        if (tid < MAXR) s_tn[tid] = d_nte[start + ((tid < cnt) ? tid : 0)];
        __syncthreads();

        float acc[MAXR];
#pragma unroll
        for (int rr = 0; rr < MAXR; rr++) acc[rr] = 0.f;

        for (int ct = 0; ct < 8; ct++) {
            const int col = ct * 512 + tid;
            float4 cf[DIMS];
#pragma unroll
            for (int d = 0; d < DIMS; d++) cf[d] = d_ftr[d * N + col];
            const float cn = d_ntr[col];
            const float xv = s_p[col];

#pragma unroll 2
            for (int rr = 0; rr < MAXR; rr++) {
                float dot = 0.f, prod = 1.f;
#pragma unroll
                for (int d = 0; d < DIMS; d++) {
                    float4 rf = tfp[d * MAXR + rr];
                    dot  = fmaf(rf.x, cf[d].x, dot);
                    prod *= fmaf(rf.z, cf[d].z, rf.y * cf[d].y);
                }
                float sq = s_tn[rr] + cn - 2.f * dot;
                acc[rr] = fmaf(__expf(-sq) * fabsf(prod), xv, acc[rr]);
            }
        }
#pragma unroll
        for (int rr = 0; rr < MAXR; rr++) {
            float v = acc[rr];
#pragma unroll
            for (int o = 16; o; o >>= 1) v += __shfl_xor_sync(0xffffffffu, v, o);
            if (lane == 0) s_part[warp * SP + rr] = v;
        }
        __syncthreads();
        if (tid < cnt) {
            float s = 0.f;
#pragma unroll
            for (int w = 0; w < NWARP; w++) s += s_part[w * SP + tid];
            out[start + tid] = s;
        }
    }
    gbar(&lsense);   // parity filler: total gbars = 2 + ITER + 1 + 1 = 36 (even)
}

// ---------------- launch ----------------
extern "C" void kernel_launch(void* const* d_in, const int* in_sizes, int n_in,
                              void* d_out, int out_size) {
    const float* Xtr = (const float*)d_in[0];
    const float* ytr = (const float*)d_in[1];
    const float* Xte = (const float*)d_in[2];
    mega_kernel<<<GRID, BLOCK>>>(Xtr, ytr, Xte, (float*)d_out);
}